// round 8
// baseline (speedup 1.0000x reference)
#include <cuda_runtime.h>
#include <cuda_fp16.h>
#include <math.h>
#include <stdint.h>

// Problem constants
constexpr int Bc  = 2;
constexpr int Sc  = 2048;
constexpr int Dc  = 2048;
constexpr int Hc  = 16;
constexpr int DHc = 128;
constexpr int Mc  = Bc * Sc;   // 4096 rows for projections

// ---------------------------------------------------------------------------
// Scratch (device globals: allocation-free per harness rules)
// ---------------------------------------------------------------------------
__device__ __half g_Qp [(size_t)Mc * Dc];      // pre-rope Q (half)
__device__ __half g_Kp [(size_t)Mc * Dc];      // pre-rope K (half)
__device__ __half g_Vh [(size_t)Mc * Dc];      // half V
__device__ __half g_xh [(size_t)Mc * Dc];
__device__ __half g_Qh [(size_t)Mc * Dc];      // roped + softmax-scaled
__device__ __half g_Kh [(size_t)Mc * Dc];      // roped
__device__ __half g_Ah [(size_t)Mc * Dc];      // attention out (half)
__device__ __half g_wqh[(size_t)Dc * Dc];
__device__ __half g_wkh[(size_t)Dc * Dc];
__device__ __half g_wvh[(size_t)Dc * Dc];
__device__ __half g_woh[(size_t)Dc * Dc];

#define CP_ASYNC16(dst, src) \
    asm volatile("cp.async.cg.shared.global [%0], [%1], 16;\n" :: "r"(dst), "l"(src))

#define MMA_F16(c, a0, a1, a2, a3, b0, b1)                                     \
    asm volatile(                                                              \
        "mma.sync.aligned.m16n8k16.row.col.f32.f16.f16.f32 "                   \
        "{%0,%1,%2,%3}, {%4,%5,%6,%7}, {%8,%9}, {%0,%1,%2,%3};\n"              \
        : "+f"((c)[0]), "+f"((c)[1]), "+f"((c)[2]), "+f"((c)[3])               \
        : "r"(a0), "r"(a1), "r"(a2), "r"(a3), "r"(b0), "r"(b1))

#define LDSM_X4(r0, r1, r2, r3, addr)                                          \
    asm volatile("ldmatrix.sync.aligned.m8n8.x4.shared.b16 {%0,%1,%2,%3}, [%4];" \
        : "=r"(r0), "=r"(r1), "=r"(r2), "=r"(r3) : "r"(addr))

#define LDSM_X4_T(r0, r1, r2, r3, addr)                                        \
    asm volatile("ldmatrix.sync.aligned.m8n8.x4.trans.shared.b16 {%0,%1,%2,%3}, [%4];" \
        : "=r"(r0), "=r"(r1), "=r"(r2), "=r"(r3) : "r"(addr))

// ---------------------------------------------------------------------------
// fp32 -> fp16 conversion (round-to-nearest)
// ---------------------------------------------------------------------------
__global__ void cvt_half(const float* __restrict__ in, __half* __restrict__ out,
                         int n4) {
    int i = blockIdx.x * blockDim.x + threadIdx.x;
    if (i >= n4) return;
    float4 v = *(const float4*)(in + (size_t)i * 4);
    __half2 h01 = __floats2half2_rn(v.x, v.y);
    __half2 h23 = __floats2half2_rn(v.z, v.w);
    uint2 u;
    u.x = *(uint32_t*)&h01;
    u.y = *(uint32_t*)&h23;
    *(uint2*)(out + (size_t)i * 4) = u;
}

// ---------------------------------------------------------------------------
// fp16 mma GEMM:  C[M,N] = A[M,K] @ B[N,K]^T  (ldmatrix + cp.async, BM=BN=128)
// ---------------------------------------------------------------------------
constexpr int HST = 40;                               // halves per smem row
constexpr int GEMM_SMEM_B = 2 * 2 * 128 * HST * 2;    // 40960 bytes

__global__ void __launch_bounds__(128) gemm_f16(const __half* __restrict__ A,
                                                const __half* __restrict__ B,
                                                float* __restrict__ Cf,
                                                __half* __restrict__ Ch,
                                                int M, int N, int K) {
    extern __shared__ __half hsm[];
    __half* sA = hsm;
    __half* sB = hsm + 2 * 128 * HST;

    const int tid  = threadIdx.x;
    const int wid  = tid >> 5;
    const int lane = tid & 31;
    const int wm = (wid & 1) * 64;
    const int wn = (wid >> 1) * 64;
    const int gp = lane >> 2;
    const int t4 = lane & 3;
    const int m0 = blockIdx.y * 128;
    const int n0 = blockIdx.x * 128;

    const int arow = (lane & 7) + ((lane >> 3) & 1) * 8;
    const int acol = (lane >> 4) * 8;
    const int brow = (lane & 7) + (lane >> 4) * 8;
    const int bcol = ((lane >> 3) & 1) * 8;

    const int lrow = tid >> 2;
    const int lseg = tid & 3;
    const __half* Ag = A + (size_t)(m0 + lrow) * K + lseg * 8;
    const __half* Bg = B + (size_t)(n0 + lrow) * K + lseg * 8;

    const uint32_t sA_u = (uint32_t)__cvta_generic_to_shared(sA);
    const uint32_t sB_u = (uint32_t)__cvta_generic_to_shared(sB);

    float acc[4][8][4];
#pragma unroll
    for (int im = 0; im < 4; im++)
#pragma unroll
        for (int in_ = 0; in_ < 8; in_++)
#pragma unroll
            for (int r = 0; r < 4; r++) acc[im][in_][r] = 0.f;

    const int nt = K / 32;

    {
#pragma unroll
        for (int p = 0; p < 4; p++) {
            int row = lrow + p * 32;
            CP_ASYNC16(sA_u + (uint32_t)((row * HST + lseg * 8) * 2),
                       Ag + (size_t)p * 32 * K);
            CP_ASYNC16(sB_u + (uint32_t)((row * HST + lseg * 8) * 2),
                       Bg + (size_t)p * 32 * K);
        }
        asm volatile("cp.async.commit_group;\n");
    }

    for (int kt = 0; kt < nt; kt++) {
        const int cur = kt & 1;
        if (kt + 1 < nt) {
            const int nb = cur ^ 1;
            const int k0 = (kt + 1) * 32;
#pragma unroll
            for (int p = 0; p < 4; p++) {
                int row = lrow + p * 32;
                CP_ASYNC16(sA_u + (uint32_t)((((nb * 128) + row) * HST + lseg * 8) * 2),
                           Ag + (size_t)p * 32 * K + k0);
                CP_ASYNC16(sB_u + (uint32_t)((((nb * 128) + row) * HST + lseg * 8) * 2),
                           Bg + (size_t)p * 32 * K + k0);
            }
            asm volatile("cp.async.commit_group;\n");
            asm volatile("cp.async.wait_group 1;\n");
        } else {
            asm volatile("cp.async.wait_group 0;\n");
        }
        __syncthreads();

        const uint32_t cA_u = sA_u + (uint32_t)(cur * 128 * HST * 2);
        const uint32_t cB_u = sB_u + (uint32_t)(cur * 128 * HST * 2);

#pragma unroll
        for (int ks = 0; ks < 2; ks++) {
            const int kk = ks * 16;
            uint32_t af[4][4];
#pragma unroll
            for (int im = 0; im < 4; im++)
                LDSM_X4(af[im][0], af[im][1], af[im][2], af[im][3],
                        cA_u + (uint32_t)(((wm + im * 16 + arow) * HST + kk + acol) * 2));
            uint32_t bf[8][2];
#pragma unroll
            for (int j2 = 0; j2 < 4; j2++)
                LDSM_X4(bf[2 * j2][0], bf[2 * j2][1],
                        bf[2 * j2 + 1][0], bf[2 * j2 + 1][1],
                        cB_u + (uint32_t)(((wn + j2 * 16 + brow) * HST + kk + bcol) * 2));
#pragma unroll
            for (int im = 0; im < 4; im++)
#pragma unroll
                for (int in_ = 0; in_ < 8; in_++)
                    MMA_F16(acc[im][in_], af[im][0], af[im][1], af[im][2],
                            af[im][3], bf[in_][0], bf[in_][1]);
        }
        __syncthreads();
    }

#pragma unroll
    for (int im = 0; im < 4; im++) {
        const int mA = m0 + wm + im * 16 + gp;
#pragma unroll
        for (int in_ = 0; in_ < 8; in_++) {
            const int n = n0 + wn + in_ * 8 + 2 * t4;
            if (Ch) {
                *(__half2*)(Ch + (size_t)mA * N + n) =
                    __floats2half2_rn(acc[im][in_][0], acc[im][in_][1]);
                *(__half2*)(Ch + (size_t)(mA + 8) * N + n) =
                    __floats2half2_rn(acc[im][in_][2], acc[im][in_][3]);
            } else {
                *(float2*)(Cf + (size_t)mA * N + n) =
                    make_float2(acc[im][in_][0], acc[im][in_][1]);
                *(float2*)(Cf + (size_t)(mA + 8) * N + n) =
                    make_float2(acc[im][in_][2], acc[im][in_][3]);
            }
        }
    }
}

// ---------------------------------------------------------------------------
// RoPE: half in, half out. Qh pre-scaled by 1/sqrt(DH).
// ---------------------------------------------------------------------------
__global__ void rope_half(const __half* __restrict__ Qf,
                          const __half* __restrict__ Kf,
                          __half* __restrict__ Qh, __half* __restrict__ Kh,
                          const float* __restrict__ cosp,
                          const float* __restrict__ sinp) {
    int i = blockIdx.x * blockDim.x + threadIdx.x;
    const int total = Bc * Sc * Hc * 32;
    if (i >= total) return;
    int d2 = (i & 31) * 2;            // 0..62
    int h  = (i >> 5) & (Hc - 1);
    int bs = i >> 9;
    int s  = bs & (Sc - 1);
    size_t base = (size_t)bs * Dc + h * DHc;

    const __half* src = blockIdx.y ? Kf : Qf;
    float2 x1 = __half22float2(*(const __half2*)(src + base + d2));
    float2 x2 = __half22float2(*(const __half2*)(src + base + d2 + 64));
    float2 c  = *(const float2*)(cosp + s * DHc + d2);
    float2 sn = *(const float2*)(sinp + s * DHc + d2);

    float r1x = x1.x * c.x - x2.x * sn.x;
    float r1y = x1.y * c.y - x2.y * sn.y;
    float r2x = x2.x * c.x + x1.x * sn.x;
    float r2y = x2.y * c.y + x1.y * sn.y;

    if (blockIdx.y == 0) {
        const float scale = 0.08838834764831845f;
        r1x *= scale; r1y *= scale; r2x *= scale; r2y *= scale;
    }
    __half* dst = blockIdx.y ? Kh : Qh;
    *(__half2*)(dst + base + d2)      = __floats2half2_rn(r1x, r1y);
    *(__half2*)(dst + base + d2 + 64) = __floats2half2_rn(r2x, r2y);
}

// ---------------------------------------------------------------------------
// Flash attention: BM=128 q rows, BN=64 kv cols, 256 thr / 8 warps
// (each warp 16 rows). fp16 mma both phases, fp32 softmax/accum.
// Double-buffered K; V overlaps QK; K(j+1) overlaps PV(j).
// ---------------------------------------------------------------------------
constexpr int QSH = 136;   // halves
constexpr int KSH = 136;
constexpr int VSH = 136;
constexpr int PSH = 72;
constexpr int OFF_Q  = 0;
constexpr int OFF_K0 = OFF_Q  + 128 * QSH * 2;       // 34816
constexpr int OFF_K1 = OFF_K0 + 64 * KSH * 2;        // 52224
constexpr int OFF_V  = OFF_K1 + 64 * KSH * 2;        // 69632
constexpr int OFF_P  = OFF_V  + 64 * VSH * 2;        // 87040
constexpr int FL_SMEM_B = OFF_P + 128 * PSH * 2;     // 105472

__global__ void __launch_bounds__(256) flash_tc(const __half* __restrict__ Q,
                                                const __half* __restrict__ K,
                                                const __half* __restrict__ V,
                                                __half* __restrict__ O) {
    extern __shared__ char smraw[];
    __half* sP = (__half*)(smraw + OFF_P);
    const uint32_t sQ_u  = (uint32_t)__cvta_generic_to_shared(smraw + OFF_Q);
    const uint32_t sK0_u = (uint32_t)__cvta_generic_to_shared(smraw + OFF_K0);
    const uint32_t sK1_u = (uint32_t)__cvta_generic_to_shared(smraw + OFF_K1);
    const uint32_t sV_u  = (uint32_t)__cvta_generic_to_shared(smraw + OFF_V);
    const uint32_t sP_u  = (uint32_t)__cvta_generic_to_shared(sP);

    const int tid  = threadIdx.x;
    const int wid  = tid >> 5;
    const int lane = tid & 31;
    const int gp   = lane >> 2;
    const int t4   = lane & 3;
    const int qb   = blockIdx.x;
    const int bh   = blockIdx.y;
    const int b    = bh >> 4;
    const int h    = bh & (Hc - 1);
    const size_t base = ((size_t)b * Sc) * Dc + (size_t)h * DHc;
    const int q0   = qb * 128;
    const int wrow = wid * 16;
    const int r0loc = wrow + gp;       // 0..127
    const int r1loc = r0loc + 8;
    const int jmax = 2 * qb + 1;

    const int arow = (lane & 7) + ((lane >> 3) & 1) * 8;
    const int acol = (lane >> 4) * 8;
    const int brow = (lane & 7) + (lane >> 4) * 8;
    const int bcol = ((lane >> 3) & 1) * 8;
    const int vrow = (lane & 7) + ((lane >> 3) & 1) * 8;
    const int vcol = (lane >> 4) * 8;

    // prologue: Q + K0 in group 0, V0 in group 1
    {
#pragma unroll
        for (int p = 0; p < 8; p++) {       // Q: 128 rows x 16 segs
            int idx = tid + p * 256;
            int r = idx >> 4, sg = (idx & 15) * 8;
            CP_ASYNC16(sQ_u + (uint32_t)((r * QSH + sg) * 2),
                       Q + base + (size_t)(q0 + r) * Dc + sg);
        }
#pragma unroll
        for (int p = 0; p < 4; p++) {       // K0: 64 rows x 16 segs
            int idx = tid + p * 256;
            int r = idx >> 4, sg = (idx & 15) * 8;
            CP_ASYNC16(sK0_u + (uint32_t)((r * KSH + sg) * 2),
                       K + base + (size_t)r * Dc + sg);
        }
        asm volatile("cp.async.commit_group;\n");
#pragma unroll
        for (int p = 0; p < 4; p++) {       // V0
            int idx = tid + p * 256;
            int r = idx >> 4, sg = (idx & 15) * 8;
            CP_ASYNC16(sV_u + (uint32_t)((r * VSH + sg) * 2),
                       V + base + (size_t)r * Dc + sg);
        }
        asm volatile("cp.async.commit_group;\n");
    }

    float o[16][4];
#pragma unroll
    for (int n = 0; n < 16; n++)
#pragma unroll
        for (int r = 0; r < 4; r++) o[n][r] = 0.f;
    float m0 = -1e30f, m1 = -1e30f, l0 = 0.f, l1 = 0.f;

    for (int j = 0; j <= jmax; ++j) {
        const uint32_t sKc_u = (j & 1) ? sK1_u : sK0_u;
        const uint32_t sKn_u = (j & 1) ? sK0_u : sK1_u;

        asm volatile("cp.async.wait_group 1;\n");
        __syncthreads();

        // ---- S = Qs @ K^T ----
        float sacc[8][4];
#pragma unroll
        for (int n = 0; n < 8; n++)
#pragma unroll
            for (int r = 0; r < 4; r++) sacc[n][r] = 0.f;

#pragma unroll
        for (int kk8 = 0; kk8 < 8; kk8++) {
            const int kk = kk8 * 16;
            uint32_t a0, a1, a2, a3;
            LDSM_X4(a0, a1, a2, a3,
                    sQ_u + (uint32_t)(((wrow + arow) * QSH + kk + acol) * 2));
            uint32_t bf[8][2];
#pragma unroll
            for (int j2 = 0; j2 < 4; j2++)
                LDSM_X4(bf[2 * j2][0], bf[2 * j2][1],
                        bf[2 * j2 + 1][0], bf[2 * j2 + 1][1],
                        sKc_u + (uint32_t)(((j2 * 16 + brow) * KSH + kk + bcol) * 2));
#pragma unroll
            for (int nt = 0; nt < 8; nt++)
                MMA_F16(sacc[nt], a0, a1, a2, a3, bf[nt][0], bf[nt][1]);
        }

        // causal mask: tiles j >= 2*qb straddle/exceed the diagonal
        if (j >= 2 * qb) {
            const int d0 = r0loc + q0 - j * 64;   // max allowed col for row 0
            const int d1 = d0 + 8;
#pragma unroll
            for (int nt = 0; nt < 8; nt++) {
                int c0 = nt * 8 + 2 * t4;
                if (c0 > d0)     sacc[nt][0] = -1e30f;
                if (c0 + 1 > d0) sacc[nt][1] = -1e30f;
                if (c0 > d1)     sacc[nt][2] = -1e30f;
                if (c0 + 1 > d1) sacc[nt][3] = -1e30f;
            }
        }

        // ---- online softmax ----
        float mx0 = -1e30f, mx1 = -1e30f;
#pragma unroll
        for (int nt = 0; nt < 8; nt++) {
            mx0 = fmaxf(mx0, fmaxf(sacc[nt][0], sacc[nt][1]));
            mx1 = fmaxf(mx1, fmaxf(sacc[nt][2], sacc[nt][3]));
        }
        mx0 = fmaxf(mx0, __shfl_xor_sync(0xffffffff, mx0, 1));
        mx0 = fmaxf(mx0, __shfl_xor_sync(0xffffffff, mx0, 2));
        mx1 = fmaxf(mx1, __shfl_xor_sync(0xffffffff, mx1, 1));
        mx1 = fmaxf(mx1, __shfl_xor_sync(0xffffffff, mx1, 2));

        float m0n = fmaxf(m0, mx0);
        float m1n = fmaxf(m1, mx1);
        float corr0 = __expf(m0 - m0n);
        float corr1 = __expf(m1 - m1n);
        m0 = m0n; m1 = m1n;

        float ls0 = 0.f, ls1 = 0.f;
#pragma unroll
        for (int nt = 0; nt < 8; nt++) {
            float p0 = __expf(sacc[nt][0] - m0);
            float p1 = __expf(sacc[nt][1] - m0);
            float p2 = __expf(sacc[nt][2] - m1);
            float p3 = __expf(sacc[nt][3] - m1);
            ls0 += p0 + p1;
            ls1 += p2 + p3;
            int c0 = nt * 8 + 2 * t4;
            *(__half2*)(sP + r0loc * PSH + c0) = __floats2half2_rn(p0, p1);
            *(__half2*)(sP + r1loc * PSH + c0) = __floats2half2_rn(p2, p3);
        }
        ls0 += __shfl_xor_sync(0xffffffff, ls0, 1);
        ls0 += __shfl_xor_sync(0xffffffff, ls0, 2);
        ls1 += __shfl_xor_sync(0xffffffff, ls1, 1);
        ls1 += __shfl_xor_sync(0xffffffff, ls1, 2);
        l0 = l0 * corr0 + ls0;
        l1 = l1 * corr1 + ls1;

#pragma unroll
        for (int nt = 0; nt < 16; nt++) {
            o[nt][0] *= corr0; o[nt][1] *= corr0;
            o[nt][2] *= corr1; o[nt][3] *= corr1;
        }

        // prefetch K_{j+1}
        if (j < jmax) {
            const int k0n = (j + 1) * 64;
#pragma unroll
            for (int p = 0; p < 4; p++) {
                int idx = tid + p * 256;
                int r = idx >> 4, sg = (idx & 15) * 8;
                CP_ASYNC16(sKn_u + (uint32_t)((r * KSH + sg) * 2),
                           K + base + (size_t)(k0n + r) * Dc + sg);
            }
            asm volatile("cp.async.commit_group;\n");
            asm volatile("cp.async.wait_group 1;\n");
        } else {
            asm volatile("cp.async.wait_group 0;\n");
        }
        __syncthreads();   // P visible + V ready

        // ---- O += P @ V ----
#pragma unroll
        for (int ks = 0; ks < 4; ks++) {
            const int kk = ks * 16;
            uint32_t a0, a1, a2, a3;
            LDSM_X4(a0, a1, a2, a3,
                    sP_u + (uint32_t)(((wrow + arow) * PSH + kk + acol) * 2));
#pragma unroll
            for (int j2 = 0; j2 < 8; j2++) {
                uint32_t b00, b01, b10, b11;
                LDSM_X4_T(b00, b01, b10, b11,
                    sV_u + (uint32_t)(((kk + vrow) * VSH + j2 * 16 + vcol) * 2));
                MMA_F16(o[2 * j2],     a0, a1, a2, a3, b00, b01);
                MMA_F16(o[2 * j2 + 1], a0, a1, a2, a3, b10, b11);
            }
        }
        __syncthreads();

        if (j < jmax) {
            const int k0n = (j + 1) * 64;
#pragma unroll
            for (int p = 0; p < 4; p++) {
                int idx = tid + p * 256;
                int r = idx >> 4, sg = (idx & 15) * 8;
                CP_ASYNC16(sV_u + (uint32_t)((r * VSH + sg) * 2),
                           V + base + (size_t)(k0n + r) * Dc + sg);
            }
            asm volatile("cp.async.commit_group;\n");
        }
    }

    // epilogue
    float inv0 = 1.0f / l0, inv1 = 1.0f / l1;
    const size_t row0 = base + (size_t)(q0 + r0loc) * Dc;
    const size_t row1 = base + (size_t)(q0 + r1loc) * Dc;
#pragma unroll
    for (int nt = 0; nt < 16; nt++) {
        int c0 = nt * 8 + 2 * t4;
        *(__half2*)(O + row0 + c0) =
            __floats2half2_rn(o[nt][0] * inv0, o[nt][1] * inv0);
        *(__half2*)(O + row1 + c0) =
            __floats2half2_rn(o[nt][2] * inv1, o[nt][3] * inv1);
    }
}

// ---------------------------------------------------------------------------
// Launch
// ---------------------------------------------------------------------------
extern "C" void kernel_launch(void* const* d_in, const int* in_sizes, int n_in,
                              void* d_out, int out_size) {
    const float* x    = (const float*)d_in[0];
    const float* cosp = (const float*)d_in[1];
    const float* sinp = (const float*)d_in[2];
    const float* Wq   = (const float*)d_in[3];
    const float* Wk   = (const float*)d_in[4];
    const float* Wv   = (const float*)d_in[5];
    const float* Wo   = (const float*)d_in[6];
    float* out = (float*)d_out;

    __half *Qp, *Kp, *Vh, *xh, *Qh, *Kh, *Ah, *wqh, *wkh, *wvh, *woh;
    cudaGetSymbolAddress((void**)&Qp, g_Qp);
    cudaGetSymbolAddress((void**)&Kp, g_Kp);
    cudaGetSymbolAddress((void**)&Vh, g_Vh);
    cudaGetSymbolAddress((void**)&xh, g_xh);
    cudaGetSymbolAddress((void**)&Qh, g_Qh);
    cudaGetSymbolAddress((void**)&Kh, g_Kh);
    cudaGetSymbolAddress((void**)&Ah, g_Ah);
    cudaGetSymbolAddress((void**)&wqh, g_wqh);
    cudaGetSymbolAddress((void**)&wkh, g_wkh);
    cudaGetSymbolAddress((void**)&wvh, g_wvh);
    cudaGetSymbolAddress((void**)&woh, g_woh);

    cudaFuncSetAttribute(gemm_f16, cudaFuncAttributeMaxDynamicSharedMemorySize,
                         GEMM_SMEM_B);
    cudaFuncSetAttribute(flash_tc, cudaFuncAttributeMaxDynamicSharedMemorySize,
                         FL_SMEM_B);

    // fp16 conversions of GEMM inputs
    {
        const int nx = Mc * Dc / 4, nw = Dc * Dc / 4;
        cvt_half<<<(nx + 255) / 256, 256>>>(x,  xh,  nx);
        cvt_half<<<(nw + 255) / 256, 256>>>(Wq, wqh, nw);
        cvt_half<<<(nw + 255) / 256, 256>>>(Wk, wkh, nw);
        cvt_half<<<(nw + 255) / 256, 256>>>(Wv, wvh, nw);
        cvt_half<<<(nw + 255) / 256, 256>>>(Wo, woh, nw);
    }

    dim3 ggrid(Dc / 128, Mc / 128);   // (16, 32)

    gemm_f16<<<ggrid, 128, GEMM_SMEM_B>>>(xh, wqh, nullptr, Qp, Mc, Dc, Dc);
    gemm_f16<<<ggrid, 128, GEMM_SMEM_B>>>(xh, wkh, nullptr, Kp, Mc, Dc, Dc);
    gemm_f16<<<ggrid, 128, GEMM_SMEM_B>>>(xh, wvh, nullptr, Vh, Mc, Dc, Dc);

    // RoPE (half -> half; Qh pre-scaled)
    {
        int total = Bc * Sc * Hc * 32;
        dim3 rgrid((total + 255) / 256, 2);
        rope_half<<<rgrid, 256>>>(Qp, Kp, Qh, Kh, cosp, sinp);
    }

    // flash attention (BM=128)
    {
        dim3 fgrid(Sc / 128, Bc * Hc);   // (16, 32)
        flash_tc<<<fgrid, 256, FL_SMEM_B>>>(Qh, Kh, Vh, Ah);
    }

    // O projection (fp32 out)
    gemm_f16<<<ggrid, 128, GEMM_SMEM_B>>>(Ah, woh, out, nullptr, Mc, Dc, Dc);
}